// round 3
// baseline (speedup 1.0000x reference)
#include <cuda_runtime.h>
#include <math.h>

#define CB     4
#define CH     56
#define CW     56
#define CDIM   512
#define CHEADS 16
#define CK     7
#define CD     32
#define CSP    (CH*CW)          // 3136
#define CM     (CB*CSP)         // 12544
#define WIN    14
#define NPOS   (WIN*WIN)        // 196

// Scratch: Q/K/V in [b, head, spatial, d] layout (25.7MB each)
__device__ float g_q[CB*CHEADS*CSP*CD];
__device__ float g_k[CB*CHEADS*CSP*CD];
__device__ float g_v[CB*CHEADS*CSP*CD];

__device__ __forceinline__ unsigned long long pack2(float x, float y) {
    unsigned long long r;
    asm("mov.b64 %0, {%1, %2};" : "=l"(r) : "f"(x), "f"(y));
    return r;
}
__device__ __forceinline__ float2 unpack2(unsigned long long v) {
    float2 r;
    asm("mov.b64 {%0, %1}, %2;" : "=f"(r.x), "=f"(r.y) : "l"(v));
    return r;
}
__device__ __forceinline__ unsigned long long ffma2(unsigned long long a,
                                                    unsigned long long b,
                                                    unsigned long long c) {
    unsigned long long d;
    asm("fma.rn.f32x2 %0, %1, %2, %3;" : "=l"(d) : "l"(a), "l"(b), "l"(c));
    return d;
}

// ---------------------------------------------------------------------------
// QKV GEMM: out[m,n] = sum_k A[m,k] * W[n,k] + bias[n]
// blockIdx.z selects Q (scaled by 1/sqrt(d)) / K / V.
// Output remapped to [b, head, spatial, d].
// ---------------------------------------------------------------------------
#define BM  128
#define BN  64
#define BKK 16
#define AS_STRIDE 130   // padded (even, 8B-aligned pairs, conflict-free)
#define BS_STRIDE 66

__global__ void __launch_bounds__(256) qkv_gemm_kernel(
    const float* __restrict__ A,
    const float* __restrict__ Wq, const float* __restrict__ bq,
    const float* __restrict__ Wk, const float* __restrict__ bk,
    const float* __restrict__ Wv, const float* __restrict__ bv)
{
    __shared__ float As[BKK * AS_STRIDE];
    __shared__ float Bs[BKK * BS_STRIDE];

    const int z = blockIdx.z;
    const float* Wm   = (z == 0) ? Wq : (z == 1) ? Wk : Wv;
    const float* bias = (z == 0) ? bq : (z == 1) ? bk : bv;
    float* outp       = (z == 0) ? g_q : (z == 1) ? g_k : g_v;

    const int m0 = blockIdx.x * BM;
    const int n0 = blockIdx.y * BN;
    const int tid = threadIdx.x;
    const int tx = tid & 15;   // col group: tx*4
    const int ty = tid >> 4;   // row group: ty*8

    unsigned long long acc[4][4];
    #pragma unroll
    for (int i2 = 0; i2 < 4; i2++)
        #pragma unroll
        for (int j = 0; j < 4; j++)
            acc[i2][j] = 0ull;

    const int ar = tid >> 2;         // 0..63
    const int ak = (tid & 3) << 2;   // 0,4,8,12

    for (int kt = 0; kt < CDIM; kt += BKK) {
        float4 a0 = *(const float4*)&A [(m0 + ar     ) * CDIM + kt + ak];
        float4 a1 = *(const float4*)&A [(m0 + ar + 64) * CDIM + kt + ak];
        float4 w0 = *(const float4*)&Wm[(n0 + ar     ) * CDIM + kt + ak];

        As[(ak+0)*AS_STRIDE + ar] = a0.x;  As[(ak+1)*AS_STRIDE + ar] = a0.y;
        As[(ak+2)*AS_STRIDE + ar] = a0.z;  As[(ak+3)*AS_STRIDE + ar] = a0.w;
        As[(ak+0)*AS_STRIDE + ar+64] = a1.x;  As[(ak+1)*AS_STRIDE + ar+64] = a1.y;
        As[(ak+2)*AS_STRIDE + ar+64] = a1.z;  As[(ak+3)*AS_STRIDE + ar+64] = a1.w;
        Bs[(ak+0)*BS_STRIDE + ar] = w0.x;  Bs[(ak+1)*BS_STRIDE + ar] = w0.y;
        Bs[(ak+2)*BS_STRIDE + ar] = w0.z;  Bs[(ak+3)*BS_STRIDE + ar] = w0.w;
        __syncthreads();

        #pragma unroll
        for (int kk = 0; kk < BKK; kk++) {
            unsigned long long a2[4];
            #pragma unroll
            for (int i2 = 0; i2 < 4; i2++)
                a2[i2] = *(const unsigned long long*)&As[kk*AS_STRIDE + ty*8 + i2*2];
            #pragma unroll
            for (int j = 0; j < 4; j++) {
                float bvv = Bs[kk*BS_STRIDE + tx*4 + j];
                unsigned long long bb = pack2(bvv, bvv);
                #pragma unroll
                for (int i2 = 0; i2 < 4; i2++)
                    acc[i2][j] = ffma2(a2[i2], bb, acc[i2][j]);
            }
        }
        __syncthreads();
    }

    // Epilogue: add bias, scale Q, remap to [b, head, sp, d]
    const float scale = (z == 0) ? 0.17677669529663688f : 1.0f;  // 1/sqrt(32)
    const int nb = n0 + tx * 4;
    float4 b4 = *(const float4*)&bias[nb];
    const int head = nb >> 5;
    const int ch   = nb & 31;

    #pragma unroll
    for (int i2 = 0; i2 < 4; i2++) {
        float2 c0 = unpack2(acc[i2][0]);
        float2 c1 = unpack2(acc[i2][1]);
        float2 c2 = unpack2(acc[i2][2]);
        float2 c3 = unpack2(acc[i2][3]);
        #pragma unroll
        for (int s = 0; s < 2; s++) {
            const int m    = m0 + ty*8 + i2*2 + s;
            const int bidx = m / CSP;
            const int sp   = m - bidx * CSP;
            float v0 = ((s ? c0.y : c0.x) + b4.x) * scale;
            float v1 = ((s ? c1.y : c1.x) + b4.y) * scale;
            float v2 = ((s ? c2.y : c2.x) + b4.z) * scale;
            float v3 = ((s ? c3.y : c3.x) + b4.w) * scale;
            float* dst = outp + ((bidx*CHEADS + head)*CSP + sp)*CD + ch;
            *(float4*)dst = make_float4(v0, v1, v2, v3);
        }
    }
}

// ---------------------------------------------------------------------------
// Neighborhood attention. One 64-thread block per (b, head, 8x8 query tile).
// K/V 14x14x32 window cached in smem with XOR-(p&7) float4 chunk swizzle
// (conflict-free LDS.128). Thread-per-query, fully register-resident.
// ---------------------------------------------------------------------------
__global__ void __launch_bounds__(64) natt_kernel(const float* __restrict__ rpb,
                                                  float* __restrict__ out)
{
    extern __shared__ float sm[];
    float* Ks   = sm;                  // NPOS*32
    float* Vs   = sm + NPOS*CD;        // NPOS*32
    float* rpbs = Vs + NPOS*CD;        // 13*13 = 169

    const int tile = blockIdx.x;       // 0..48 (7x7 tiles)
    const int ti = tile / 7, tj = tile - ti*7;
    const int h = blockIdx.y, b = blockIdx.z;
    const int i0 = ti*8, j0 = tj*8;
    const int r0 = min(max(i0 - 3, 0), CH - WIN);
    const int c0 = min(max(j0 - 3, 0), CW - WIN);
    const int tid = threadIdx.x;

    for (int idx = tid; idx < (2*CK-1)*(2*CK-1); idx += 64)
        rpbs[idx] = rpb[h*(2*CK-1)*(2*CK-1) + idx];

    const float* kb = g_k + (b*CHEADS + h) * CSP * CD;
    const float* vb = g_v + (b*CHEADS + h) * CSP * CD;

    // 14 rows x (14 cols x 32 d) contiguous per row; 1568 float4 per array
    for (int idx = tid; idx < WIN*WIN*8; idx += 64) {
        int row = idx / (WIN*8);
        int rem = idx - row*(WIN*8);
        int col = rem >> 3;
        int d4  = rem & 7;
        int goff = ((r0 + row)*CW + (c0 + col))*CD + d4*4;
        int p    = row*WIN + col;
        int soff = p*CD + ((d4 ^ (p & 7)) << 2);
        *(float4*)&Ks[soff] = *(const float4*)&kb[goff];
        *(float4*)&Vs[soff] = *(const float4*)&vb[goff];
    }
    __syncthreads();

    const int qi = tid >> 3, qj = tid & 7;
    const int i = i0 + qi, j = j0 + qj;
    const int ni = min(max(i - 3, 0), CH - CK);
    const int nj = min(max(j - 3, 0), CW - CK);
    const int rl = ni - r0, cl = nj - c0;
    const int dbi = ni - i + (CK - 1), dbj = nj - j + (CK - 1);

    float4 q4[8];
    {
        const float* qp = g_q + ((b*CHEADS + h)*CSP + i*CW + j)*CD;
        #pragma unroll
        for (int d4 = 0; d4 < 8; d4++) q4[d4] = *(const float4*)&qp[d4*4];
    }

    float sc[CK*CK];
    #pragma unroll
    for (int ki = 0; ki < CK; ki++) {
        #pragma unroll
        for (int kj = 0; kj < CK; kj++) {
            const int p  = (rl + ki)*WIN + (cl + kj);
            const int sw = p & 7;
            const float* kp = Ks + p*CD;
            float s = 0.f;
            #pragma unroll
            for (int d4 = 0; d4 < 8; d4++) {
                float4 kk = *(const float4*)&kp[(d4 ^ sw) << 2];
                s += q4[d4].x*kk.x + q4[d4].y*kk.y + q4[d4].z*kk.z + q4[d4].w*kk.w;
            }
            sc[ki*CK + kj] = s + rpbs[(dbi + ki)*(2*CK-1) + (dbj + kj)];
        }
    }

    float mx = sc[0];
    #pragma unroll
    for (int t = 1; t < CK*CK; t++) mx = fmaxf(mx, sc[t]);
    float sum = 0.f;
    #pragma unroll
    for (int t = 0; t < CK*CK; t++) { float e = __expf(sc[t] - mx); sc[t] = e; sum += e; }
    const float inv = 1.f / sum;

    float4 c4[8];
    #pragma unroll
    for (int d4 = 0; d4 < 8; d4++) c4[d4] = make_float4(0.f, 0.f, 0.f, 0.f);

    #pragma unroll
    for (int ki = 0; ki < CK; ki++) {
        #pragma unroll
        for (int kj = 0; kj < CK; kj++) {
            const int p  = (rl + ki)*WIN + (cl + kj);
            const int sw = p & 7;
            const float* vp = Vs + p*CD;
            const float w = sc[ki*CK + kj];
            #pragma unroll
            for (int d4 = 0; d4 < 8; d4++) {
                float4 vv = *(const float4*)&vp[(d4 ^ sw) << 2];
                c4[d4].x += w*vv.x; c4[d4].y += w*vv.y;
                c4[d4].z += w*vv.z; c4[d4].w += w*vv.w;
            }
        }
    }

    float* op = out + ((b*CH + i)*CW + j)*CDIM + h*CD;
    #pragma unroll
    for (int d4 = 0; d4 < 8; d4++) {
        *(float4*)&op[d4*4] = make_float4(c4[d4].x*inv, c4[d4].y*inv,
                                          c4[d4].z*inv, c4[d4].w*inv);
    }
}

// ---------------------------------------------------------------------------
extern "C" void kernel_launch(void* const* d_in, const int* in_sizes, int n_in,
                              void* d_out, int out_size)
{
    const float* hidden = (const float*)d_in[0];
    const float* Wq = (const float*)d_in[1];
    const float* bq = (const float*)d_in[2];
    const float* Wk = (const float*)d_in[3];
    const float* bk = (const float*)d_in[4];
    const float* Wv = (const float*)d_in[5];
    const float* bv = (const float*)d_in[6];
    const float* rpb = (const float*)d_in[7];

    qkv_gemm_kernel<<<dim3(CM/BM, CDIM/BN, 3), 256>>>(hidden, Wq, bq, Wk, bk, Wv, bv);

    const int smem = (2*NPOS*CD + (2*CK-1)*(2*CK-1)) * (int)sizeof(float); // 50852 B
    cudaFuncSetAttribute(natt_kernel, cudaFuncAttributeMaxDynamicSharedMemorySize, smem);
    natt_kernel<<<dim3(49, CHEADS, CB), 64, smem>>>(rpb, (float*)d_out);
}

// round 4
// speedup vs baseline: 1.0019x; 1.0019x over previous
#include <cuda_runtime.h>
#include <math.h>

#define CB     4
#define CH     56
#define CW     56
#define CDIM   512
#define CHEADS 16
#define CK     7
#define CD     32
#define CSP    (CH*CW)          // 3136
#define CM     (CB*CSP)         // 12544
#define WIN    14
#define NPOS   (WIN*WIN)        // 196

// Scratch: Q/K/V in [b, head, spatial, d] layout (25.7MB each)
__device__ float g_q[CB*CHEADS*CSP*CD];
__device__ float g_k[CB*CHEADS*CSP*CD];
__device__ float g_v[CB*CHEADS*CSP*CD];

__device__ __forceinline__ unsigned long long pack2(float x, float y) {
    unsigned long long r;
    asm("mov.b64 %0, {%1, %2};" : "=l"(r) : "f"(x), "f"(y));
    return r;
}
__device__ __forceinline__ float2 unpack2(unsigned long long v) {
    float2 r;
    asm("mov.b64 {%0, %1}, %2;" : "=f"(r.x), "=f"(r.y) : "l"(v));
    return r;
}
__device__ __forceinline__ unsigned long long ffma2(unsigned long long a,
                                                    unsigned long long b,
                                                    unsigned long long c) {
    unsigned long long d;
    asm("fma.rn.f32x2 %0, %1, %2, %3;" : "=l"(d) : "l"(a), "l"(b), "l"(c));
    return d;
}

// ---------------------------------------------------------------------------
// QKV GEMM: out[m,n] = sum_k A[m,k] * W[n,k] + bias[n]
// blockIdx.z selects Q (scaled by 1/sqrt(d)) / K / V.
// Output remapped to [b, head, spatial, d].
// ---------------------------------------------------------------------------
#define BM  128
#define BN  64
#define BKK 16
#define AS_STRIDE 130   // padded (even, 8B-aligned pairs, conflict-free)
#define BS_STRIDE 66

__global__ void __launch_bounds__(256) qkv_gemm_kernel(
    const float* __restrict__ A,
    const float* __restrict__ Wq, const float* __restrict__ bq,
    const float* __restrict__ Wk, const float* __restrict__ bk,
    const float* __restrict__ Wv, const float* __restrict__ bv)
{
    __shared__ float As[BKK * AS_STRIDE];
    __shared__ float Bs[BKK * BS_STRIDE];

    const int z = blockIdx.z;
    const float* Wm   = (z == 0) ? Wq : (z == 1) ? Wk : Wv;
    const float* bias = (z == 0) ? bq : (z == 1) ? bk : bv;
    float* outp       = (z == 0) ? g_q : (z == 1) ? g_k : g_v;

    const int m0 = blockIdx.x * BM;
    const int n0 = blockIdx.y * BN;
    const int tid = threadIdx.x;
    const int tx = tid & 15;   // col group: tx*4
    const int ty = tid >> 4;   // row group: ty*8

    unsigned long long acc[4][4];
    #pragma unroll
    for (int i2 = 0; i2 < 4; i2++)
        #pragma unroll
        for (int j = 0; j < 4; j++)
            acc[i2][j] = 0ull;

    const int ar = tid >> 2;         // 0..63
    const int ak = (tid & 3) << 2;   // 0,4,8,12

    for (int kt = 0; kt < CDIM; kt += BKK) {
        float4 a0 = *(const float4*)&A [(m0 + ar     ) * CDIM + kt + ak];
        float4 a1 = *(const float4*)&A [(m0 + ar + 64) * CDIM + kt + ak];
        float4 w0 = *(const float4*)&Wm[(n0 + ar     ) * CDIM + kt + ak];

        As[(ak+0)*AS_STRIDE + ar] = a0.x;  As[(ak+1)*AS_STRIDE + ar] = a0.y;
        As[(ak+2)*AS_STRIDE + ar] = a0.z;  As[(ak+3)*AS_STRIDE + ar] = a0.w;
        As[(ak+0)*AS_STRIDE + ar+64] = a1.x;  As[(ak+1)*AS_STRIDE + ar+64] = a1.y;
        As[(ak+2)*AS_STRIDE + ar+64] = a1.z;  As[(ak+3)*AS_STRIDE + ar+64] = a1.w;
        Bs[(ak+0)*BS_STRIDE + ar] = w0.x;  Bs[(ak+1)*BS_STRIDE + ar] = w0.y;
        Bs[(ak+2)*BS_STRIDE + ar] = w0.z;  Bs[(ak+3)*BS_STRIDE + ar] = w0.w;
        __syncthreads();

        #pragma unroll
        for (int kk = 0; kk < BKK; kk++) {
            unsigned long long a2[4];
            #pragma unroll
            for (int i2 = 0; i2 < 4; i2++)
                a2[i2] = *(const unsigned long long*)&As[kk*AS_STRIDE + ty*8 + i2*2];
            #pragma unroll
            for (int j = 0; j < 4; j++) {
                float bvv = Bs[kk*BS_STRIDE + tx*4 + j];
                unsigned long long bb = pack2(bvv, bvv);
                #pragma unroll
                for (int i2 = 0; i2 < 4; i2++)
                    acc[i2][j] = ffma2(a2[i2], bb, acc[i2][j]);
            }
        }
        __syncthreads();
    }

    // Epilogue: add bias, scale Q, remap to [b, head, sp, d]
    const float scale = (z == 0) ? 0.17677669529663688f : 1.0f;  // 1/sqrt(32)
    const int nb = n0 + tx * 4;
    float4 b4 = *(const float4*)&bias[nb];
    const int head = nb >> 5;
    const int ch   = nb & 31;

    #pragma unroll
    for (int i2 = 0; i2 < 4; i2++) {
        float2 c0 = unpack2(acc[i2][0]);
        float2 c1 = unpack2(acc[i2][1]);
        float2 c2 = unpack2(acc[i2][2]);
        float2 c3 = unpack2(acc[i2][3]);
        #pragma unroll
        for (int s = 0; s < 2; s++) {
            const int m    = m0 + ty*8 + i2*2 + s;
            const int bidx = m / CSP;
            const int sp   = m - bidx * CSP;
            float v0 = ((s ? c0.y : c0.x) + b4.x) * scale;
            float v1 = ((s ? c1.y : c1.x) + b4.y) * scale;
            float v2 = ((s ? c2.y : c2.x) + b4.z) * scale;
            float v3 = ((s ? c3.y : c3.x) + b4.w) * scale;
            float* dst = outp + ((bidx*CHEADS + head)*CSP + sp)*CD + ch;
            *(float4*)dst = make_float4(v0, v1, v2, v3);
        }
    }
}

// ---------------------------------------------------------------------------
// Neighborhood attention. One 64-thread block per (b, head, 8x8 query tile).
// K/V 14x14x32 window cached in smem with XOR-(p&7) float4 chunk swizzle
// (conflict-free LDS.128). Thread-per-query, fully register-resident.
// ---------------------------------------------------------------------------
__global__ void __launch_bounds__(64) natt_kernel(const float* __restrict__ rpb,
                                                  float* __restrict__ out)
{
    extern __shared__ float sm[];
    float* Ks   = sm;                  // NPOS*32
    float* Vs   = sm + NPOS*CD;        // NPOS*32
    float* rpbs = Vs + NPOS*CD;        // 13*13 = 169

    const int tile = blockIdx.x;       // 0..48 (7x7 tiles)
    const int ti = tile / 7, tj = tile - ti*7;
    const int h = blockIdx.y, b = blockIdx.z;
    const int i0 = ti*8, j0 = tj*8;
    const int r0 = min(max(i0 - 3, 0), CH - WIN);
    const int c0 = min(max(j0 - 3, 0), CW - WIN);
    const int tid = threadIdx.x;

    for (int idx = tid; idx < (2*CK-1)*(2*CK-1); idx += 64)
        rpbs[idx] = rpb[h*(2*CK-1)*(2*CK-1) + idx];

    const float* kb = g_k + (b*CHEADS + h) * CSP * CD;
    const float* vb = g_v + (b*CHEADS + h) * CSP * CD;

    // 14 rows x (14 cols x 32 d) contiguous per row; 1568 float4 per array
    for (int idx = tid; idx < WIN*WIN*8; idx += 64) {
        int row = idx / (WIN*8);
        int rem = idx - row*(WIN*8);
        int col = rem >> 3;
        int d4  = rem & 7;
        int goff = ((r0 + row)*CW + (c0 + col))*CD + d4*4;
        int p    = row*WIN + col;
        int soff = p*CD + ((d4 ^ (p & 7)) << 2);
        *(float4*)&Ks[soff] = *(const float4*)&kb[goff];
        *(float4*)&Vs[soff] = *(const float4*)&vb[goff];
    }
    __syncthreads();

    const int qi = tid >> 3, qj = tid & 7;
    const int i = i0 + qi, j = j0 + qj;
    const int ni = min(max(i - 3, 0), CH - CK);
    const int nj = min(max(j - 3, 0), CW - CK);
    const int rl = ni - r0, cl = nj - c0;
    const int dbi = ni - i + (CK - 1), dbj = nj - j + (CK - 1);

    float4 q4[8];
    {
        const float* qp = g_q + ((b*CHEADS + h)*CSP + i*CW + j)*CD;
        #pragma unroll
        for (int d4 = 0; d4 < 8; d4++) q4[d4] = *(const float4*)&qp[d4*4];
    }

    float sc[CK*CK];
    #pragma unroll
    for (int ki = 0; ki < CK; ki++) {
        #pragma unroll
        for (int kj = 0; kj < CK; kj++) {
            const int p  = (rl + ki)*WIN + (cl + kj);
            const int sw = p & 7;
            const float* kp = Ks + p*CD;
            float s = 0.f;
            #pragma unroll
            for (int d4 = 0; d4 < 8; d4++) {
                float4 kk = *(const float4*)&kp[(d4 ^ sw) << 2];
                s += q4[d4].x*kk.x + q4[d4].y*kk.y + q4[d4].z*kk.z + q4[d4].w*kk.w;
            }
            sc[ki*CK + kj] = s + rpbs[(dbi + ki)*(2*CK-1) + (dbj + kj)];
        }
    }

    float mx = sc[0];
    #pragma unroll
    for (int t = 1; t < CK*CK; t++) mx = fmaxf(mx, sc[t]);
    float sum = 0.f;
    #pragma unroll
    for (int t = 0; t < CK*CK; t++) { float e = __expf(sc[t] - mx); sc[t] = e; sum += e; }
    const float inv = 1.f / sum;

    float4 c4[8];
    #pragma unroll
    for (int d4 = 0; d4 < 8; d4++) c4[d4] = make_float4(0.f, 0.f, 0.f, 0.f);

    #pragma unroll
    for (int ki = 0; ki < CK; ki++) {
        #pragma unroll
        for (int kj = 0; kj < CK; kj++) {
            const int p  = (rl + ki)*WIN + (cl + kj);
            const int sw = p & 7;
            const float* vp = Vs + p*CD;
            const float w = sc[ki*CK + kj];
            #pragma unroll
            for (int d4 = 0; d4 < 8; d4++) {
                float4 vv = *(const float4*)&vp[(d4 ^ sw) << 2];
                c4[d4].x += w*vv.x; c4[d4].y += w*vv.y;
                c4[d4].z += w*vv.z; c4[d4].w += w*vv.w;
            }
        }
    }

    float* op = out + ((b*CH + i)*CW + j)*CDIM + h*CD;
    #pragma unroll
    for (int d4 = 0; d4 < 8; d4++) {
        *(float4*)&op[d4*4] = make_float4(c4[d4].x*inv, c4[d4].y*inv,
                                          c4[d4].z*inv, c4[d4].w*inv);
    }
}

// ---------------------------------------------------------------------------
extern "C" void kernel_launch(void* const* d_in, const int* in_sizes, int n_in,
                              void* d_out, int out_size)
{
    const float* hidden = (const float*)d_in[0];
    const float* Wq = (const float*)d_in[1];
    const float* bq = (const float*)d_in[2];
    const float* Wk = (const float*)d_in[3];
    const float* bk = (const float*)d_in[4];
    const float* Wv = (const float*)d_in[5];
    const float* bv = (const float*)d_in[6];
    const float* rpb = (const float*)d_in[7];

    qkv_gemm_kernel<<<dim3(CM/BM, CDIM/BN, 3), 256>>>(hidden, Wq, bq, Wk, bk, Wv, bv);

    const int smem = (2*NPOS*CD + (2*CK-1)*(2*CK-1)) * (int)sizeof(float); // 50852 B
    cudaFuncSetAttribute(natt_kernel, cudaFuncAttributeMaxDynamicSharedMemorySize, smem);
    natt_kernel<<<dim3(49, CHEADS, CB), 64, smem>>>(rpb, (float*)d_out);
}

// round 5
// speedup vs baseline: 1.0024x; 1.0005x over previous
#include <cuda_runtime.h>
#include <math.h>

#define CB     4
#define CH     56
#define CW     56
#define CDIM   512
#define CHEADS 16
#define CK     7
#define CD     32
#define CSP    (CH*CW)          // 3136
#define CM     (CB*CSP)         // 12544
#define WIN    14
#define NPOS   (WIN*WIN)        // 196

// Scratch: Q/K/V in [b, head, spatial, d] layout (25.7MB each)
__device__ float g_q[CB*CHEADS*CSP*CD];
__device__ float g_k[CB*CHEADS*CSP*CD];
__device__ float g_v[CB*CHEADS*CSP*CD];

__device__ __forceinline__ unsigned long long pack2(float x, float y) {
    unsigned long long r;
    asm("mov.b64 %0, {%1, %2};" : "=l"(r) : "f"(x), "f"(y));
    return r;
}
__device__ __forceinline__ float2 unpack2(unsigned long long v) {
    float2 r;
    asm("mov.b64 {%0, %1}, %2;" : "=f"(r.x), "=f"(r.y) : "l"(v));
    return r;
}
__device__ __forceinline__ unsigned long long ffma2(unsigned long long a,
                                                    unsigned long long b,
                                                    unsigned long long c) {
    unsigned long long d;
    asm("fma.rn.f32x2 %0, %1, %2, %3;" : "=l"(d) : "l"(a), "l"(b), "l"(c));
    return d;
}

// ---------------------------------------------------------------------------
// QKV GEMM: out[m,n] = sum_k A[m,k] * W[n,k] + bias[n]
// blockIdx.z selects Q (scaled by 1/sqrt(d)) / K / V.
// Output remapped to [b, head, spatial, d].
// ---------------------------------------------------------------------------
#define BM  128
#define BN  64
#define BKK 16
#define AS_STRIDE 130   // padded (even, 8B-aligned pairs, conflict-free)
#define BS_STRIDE 66

__global__ void __launch_bounds__(256) qkv_gemm_kernel(
    const float* __restrict__ A,
    const float* __restrict__ Wq, const float* __restrict__ bq,
    const float* __restrict__ Wk, const float* __restrict__ bk,
    const float* __restrict__ Wv, const float* __restrict__ bv)
{
    __shared__ float As[BKK * AS_STRIDE];
    __shared__ float Bs[BKK * BS_STRIDE];

    const int z = blockIdx.z;
    const float* Wm   = (z == 0) ? Wq : (z == 1) ? Wk : Wv;
    const float* bias = (z == 0) ? bq : (z == 1) ? bk : bv;
    float* outp       = (z == 0) ? g_q : (z == 1) ? g_k : g_v;

    const int m0 = blockIdx.x * BM;
    const int n0 = blockIdx.y * BN;
    const int tid = threadIdx.x;
    const int tx = tid & 15;   // col group: tx*4
    const int ty = tid >> 4;   // row group: ty*8

    unsigned long long acc[4][4];
    #pragma unroll
    for (int i2 = 0; i2 < 4; i2++)
        #pragma unroll
        for (int j = 0; j < 4; j++)
            acc[i2][j] = 0ull;

    const int ar = tid >> 2;         // 0..63
    const int ak = (tid & 3) << 2;   // 0,4,8,12

    for (int kt = 0; kt < CDIM; kt += BKK) {
        float4 a0 = *(const float4*)&A [(m0 + ar     ) * CDIM + kt + ak];
        float4 a1 = *(const float4*)&A [(m0 + ar + 64) * CDIM + kt + ak];
        float4 w0 = *(const float4*)&Wm[(n0 + ar     ) * CDIM + kt + ak];

        As[(ak+0)*AS_STRIDE + ar] = a0.x;  As[(ak+1)*AS_STRIDE + ar] = a0.y;
        As[(ak+2)*AS_STRIDE + ar] = a0.z;  As[(ak+3)*AS_STRIDE + ar] = a0.w;
        As[(ak+0)*AS_STRIDE + ar+64] = a1.x;  As[(ak+1)*AS_STRIDE + ar+64] = a1.y;
        As[(ak+2)*AS_STRIDE + ar+64] = a1.z;  As[(ak+3)*AS_STRIDE + ar+64] = a1.w;
        Bs[(ak+0)*BS_STRIDE + ar] = w0.x;  Bs[(ak+1)*BS_STRIDE + ar] = w0.y;
        Bs[(ak+2)*BS_STRIDE + ar] = w0.z;  Bs[(ak+3)*BS_STRIDE + ar] = w0.w;
        __syncthreads();

        #pragma unroll
        for (int kk = 0; kk < BKK; kk++) {
            unsigned long long a2[4];
            #pragma unroll
            for (int i2 = 0; i2 < 4; i2++)
                a2[i2] = *(const unsigned long long*)&As[kk*AS_STRIDE + ty*8 + i2*2];
            #pragma unroll
            for (int j = 0; j < 4; j++) {
                float bvv = Bs[kk*BS_STRIDE + tx*4 + j];
                unsigned long long bb = pack2(bvv, bvv);
                #pragma unroll
                for (int i2 = 0; i2 < 4; i2++)
                    acc[i2][j] = ffma2(a2[i2], bb, acc[i2][j]);
            }
        }
        __syncthreads();
    }

    // Epilogue: add bias, scale Q, remap to [b, head, sp, d]
    const float scale = (z == 0) ? 0.17677669529663688f : 1.0f;  // 1/sqrt(32)
    const int nb = n0 + tx * 4;
    float4 b4 = *(const float4*)&bias[nb];
    const int head = nb >> 5;
    const int ch   = nb & 31;

    #pragma unroll
    for (int i2 = 0; i2 < 4; i2++) {
        float2 c0 = unpack2(acc[i2][0]);
        float2 c1 = unpack2(acc[i2][1]);
        float2 c2 = unpack2(acc[i2][2]);
        float2 c3 = unpack2(acc[i2][3]);
        #pragma unroll
        for (int s = 0; s < 2; s++) {
            const int m    = m0 + ty*8 + i2*2 + s;
            const int bidx = m / CSP;
            const int sp   = m - bidx * CSP;
            float v0 = ((s ? c0.y : c0.x) + b4.x) * scale;
            float v1 = ((s ? c1.y : c1.x) + b4.y) * scale;
            float v2 = ((s ? c2.y : c2.x) + b4.z) * scale;
            float v3 = ((s ? c3.y : c3.x) + b4.w) * scale;
            float* dst = outp + ((bidx*CHEADS + head)*CSP + sp)*CD + ch;
            *(float4*)dst = make_float4(v0, v1, v2, v3);
        }
    }
}

// ---------------------------------------------------------------------------
// Neighborhood attention. One 64-thread block per (b, head, 8x8 query tile).
// K/V 14x14x32 window cached in smem with XOR-(p&7) float4 chunk swizzle
// (conflict-free LDS.128). Thread-per-query, fully register-resident.
// ---------------------------------------------------------------------------
__global__ void __launch_bounds__(64) natt_kernel(const float* __restrict__ rpb,
                                                  float* __restrict__ out)
{
    extern __shared__ float sm[];
    float* Ks   = sm;                  // NPOS*32
    float* Vs   = sm + NPOS*CD;        // NPOS*32
    float* rpbs = Vs + NPOS*CD;        // 13*13 = 169

    const int tile = blockIdx.x;       // 0..48 (7x7 tiles)
    const int ti = tile / 7, tj = tile - ti*7;
    const int h = blockIdx.y, b = blockIdx.z;
    const int i0 = ti*8, j0 = tj*8;
    const int r0 = min(max(i0 - 3, 0), CH - WIN);
    const int c0 = min(max(j0 - 3, 0), CW - WIN);
    const int tid = threadIdx.x;

    for (int idx = tid; idx < (2*CK-1)*(2*CK-1); idx += 64)
        rpbs[idx] = rpb[h*(2*CK-1)*(2*CK-1) + idx];

    const float* kb = g_k + (b*CHEADS + h) * CSP * CD;
    const float* vb = g_v + (b*CHEADS + h) * CSP * CD;

    // 14 rows x (14 cols x 32 d) contiguous per row; 1568 float4 per array
    for (int idx = tid; idx < WIN*WIN*8; idx += 64) {
        int row = idx / (WIN*8);
        int rem = idx - row*(WIN*8);
        int col = rem >> 3;
        int d4  = rem & 7;
        int goff = ((r0 + row)*CW + (c0 + col))*CD + d4*4;
        int p    = row*WIN + col;
        int soff = p*CD + ((d4 ^ (p & 7)) << 2);
        *(float4*)&Ks[soff] = *(const float4*)&kb[goff];
        *(float4*)&Vs[soff] = *(const float4*)&vb[goff];
    }
    __syncthreads();

    const int qi = tid >> 3, qj = tid & 7;
    const int i = i0 + qi, j = j0 + qj;
    const int ni = min(max(i - 3, 0), CH - CK);
    const int nj = min(max(j - 3, 0), CW - CK);
    const int rl = ni - r0, cl = nj - c0;
    const int dbi = ni - i + (CK - 1), dbj = nj - j + (CK - 1);

    float4 q4[8];
    {
        const float* qp = g_q + ((b*CHEADS + h)*CSP + i*CW + j)*CD;
        #pragma unroll
        for (int d4 = 0; d4 < 8; d4++) q4[d4] = *(const float4*)&qp[d4*4];
    }

    float sc[CK*CK];
    #pragma unroll
    for (int ki = 0; ki < CK; ki++) {
        #pragma unroll
        for (int kj = 0; kj < CK; kj++) {
            const int p  = (rl + ki)*WIN + (cl + kj);
            const int sw = p & 7;
            const float* kp = Ks + p*CD;
            float s = 0.f;
            #pragma unroll
            for (int d4 = 0; d4 < 8; d4++) {
                float4 kk = *(const float4*)&kp[(d4 ^ sw) << 2];
                s += q4[d4].x*kk.x + q4[d4].y*kk.y + q4[d4].z*kk.z + q4[d4].w*kk.w;
            }
            sc[ki*CK + kj] = s + rpbs[(dbi + ki)*(2*CK-1) + (dbj + kj)];
        }
    }

    float mx = sc[0];
    #pragma unroll
    for (int t = 1; t < CK*CK; t++) mx = fmaxf(mx, sc[t]);
    float sum = 0.f;
    #pragma unroll
    for (int t = 0; t < CK*CK; t++) { float e = __expf(sc[t] - mx); sc[t] = e; sum += e; }
    const float inv = 1.f / sum;

    float4 c4[8];
    #pragma unroll
    for (int d4 = 0; d4 < 8; d4++) c4[d4] = make_float4(0.f, 0.f, 0.f, 0.f);

    #pragma unroll
    for (int ki = 0; ki < CK; ki++) {
        #pragma unroll
        for (int kj = 0; kj < CK; kj++) {
            const int p  = (rl + ki)*WIN + (cl + kj);
            const int sw = p & 7;
            const float* vp = Vs + p*CD;
            const float w = sc[ki*CK + kj];
            #pragma unroll
            for (int d4 = 0; d4 < 8; d4++) {
                float4 vv = *(const float4*)&vp[(d4 ^ sw) << 2];
                c4[d4].x += w*vv.x; c4[d4].y += w*vv.y;
                c4[d4].z += w*vv.z; c4[d4].w += w*vv.w;
            }
        }
    }

    float* op = out + ((b*CH + i)*CW + j)*CDIM + h*CD;
    #pragma unroll
    for (int d4 = 0; d4 < 8; d4++) {
        *(float4*)&op[d4*4] = make_float4(c4[d4].x*inv, c4[d4].y*inv,
                                          c4[d4].z*inv, c4[d4].w*inv);
    }
}

// ---------------------------------------------------------------------------
extern "C" void kernel_launch(void* const* d_in, const int* in_sizes, int n_in,
                              void* d_out, int out_size)
{
    const float* hidden = (const float*)d_in[0];
    const float* Wq = (const float*)d_in[1];
    const float* bq = (const float*)d_in[2];
    const float* Wk = (const float*)d_in[3];
    const float* bk = (const float*)d_in[4];
    const float* Wv = (const float*)d_in[5];
    const float* bv = (const float*)d_in[6];
    const float* rpb = (const float*)d_in[7];

    qkv_gemm_kernel<<<dim3(CM/BM, CDIM/BN, 3), 256>>>(hidden, Wq, bq, Wk, bk, Wv, bv);

    const int smem = (2*NPOS*CD + (2*CK-1)*(2*CK-1)) * (int)sizeof(float); // 50852 B
    cudaFuncSetAttribute(natt_kernel, cudaFuncAttributeMaxDynamicSharedMemorySize, smem);
    natt_kernel<<<dim3(49, CHEADS, CB), 64, smem>>>(rpb, (float*)d_out);
}